// round 17
// baseline (speedup 1.0000x reference)
#include <cuda_runtime.h>
#include <cstdint>
#include <float.h>

// Problem constants (fixed by the dataset)
#define DDIM   256
#define NROWS  16384
#define KCODES 8192

// Tensor-tile config (int8 IMMA m16n8k32)
#define BM 128
#define BN 128
#define KS 64                    // K (bytes) per pipeline stage
#define NSTEPS (DDIM / KS)       // 4
#define THREADS 256
#define ASTRIDE 80               // smem bytes per tile row (conflict-free)
#define STG_B (128 * ASTRIDE)    // bytes per matrix per stage (10240)
#define ESTRIDE 129              // epilogue d2 smem stride (conflict-free scan)
#define SMEM_BYTES (128 * ESTRIDE * 4)   // 66048 (>= 4*STG_B = 40960)
#define CAP 320

typedef unsigned long long u64;
typedef unsigned int u32;

// Scratch (static device memory only; no allocations anywhere)
__device__ float  g_x2[NROWS];
__device__ float  g_w2[KCODES];
__device__ u64    g_key[NROWS];
__device__ int    g_cnt[NROWS];
__device__ u64    g_list[(size_t)NROWS * CAP];
__device__ float  g_ex[NROWS];            // ||x - dequant(q_x)|| per row
__device__ u32    g_amax[2];              // bits of max|x|, max|w|
__device__ u32    g_maxw[2];              // bits of max||w_hat||, max||delta_w||
__device__ char   g_xq[(size_t)NROWS * DDIM];
__device__ char   g_wq[(size_t)KCODES * DDIM];

// ---------------------------------------------------------------------------
// Helpers
// ---------------------------------------------------------------------------
__device__ __forceinline__ u32 smem_u32(const void* p) {
    u32 a; asm("{ .reg .u64 t; cvta.to.shared.u64 t, %1; cvt.u32.u64 %0, t; }"
               : "=r"(a) : "l"(p));
    return a;
}
__device__ __forceinline__ void cp16(u32 dst, const void* src) {
    asm volatile("cp.async.ca.shared.global [%0], [%1], 16;" :: "r"(dst), "l"(src));
}
__device__ __forceinline__ void cp_commit() { asm volatile("cp.async.commit_group;"); }
__device__ __forceinline__ void cp_wait1()  { asm volatile("cp.async.wait_group 1;"); }
__device__ __forceinline__ void cp_wait0()  { asm volatile("cp.async.wait_group 0;"); }

// m16n8k32 s8 IMMA with s32 accumulate (sm_80-base PTX)
__device__ __forceinline__ void mma_s8(int c[4], const u32 a[4], const u32 b[2]) {
    asm volatile(
        "mma.sync.aligned.m16n8k32.row.col.s32.s8.s8.s32 "
        "{%0,%1,%2,%3}, {%4,%5,%6,%7}, {%8,%9}, {%0,%1,%2,%3};"
        : "+r"(c[0]), "+r"(c[1]), "+r"(c[2]), "+r"(c[3])
        : "r"(a[0]), "r"(a[1]), "r"(a[2]), "r"(a[3]), "r"(b[0]), "r"(b[1]));
}

// ---------------------------------------------------------------------------
// Strict sequential fp32 sum of squares per row (sets the exact dist2
// rounding/tie pattern). which==0 also re-inits all per-replay scratch.
// ---------------------------------------------------------------------------
__global__ void rowsq_kernel(const float* __restrict__ in, int rows, int which)
{
    int r = blockIdx.x * blockDim.x + threadIdx.x;
    if (r >= rows) return;
    const float4* p = (const float4*)(in + (size_t)r * DDIM);
    float s = 0.0f;
#pragma unroll 8
    for (int i = 0; i < DDIM / 4; i++) {
        float4 v = p[i];
        s = __fadd_rn(s, __fmul_rn(v.x, v.x));
        s = __fadd_rn(s, __fmul_rn(v.y, v.y));
        s = __fadd_rn(s, __fmul_rn(v.z, v.z));
        s = __fadd_rn(s, __fmul_rn(v.w, v.w));
    }
    if (which) g_w2[r] = s;
    else {
        g_x2[r] = s; g_key[r] = ~0ULL; g_cnt[r] = 0;
        if (r == 0) {
            g_amax[0] = 0; g_amax[1] = 0;
            g_maxw[0] = 0; g_maxw[1] = 0;
        }
    }
}

// global max|v| (positive float bits -> unsigned atomicMax is order-correct)
__global__ void amax_kernel(const float4* __restrict__ in, int n4, int which)
{
    int i = blockIdx.x * blockDim.x + threadIdx.x;
    float m = 0.0f;
    if (i < n4) {
        float4 v = in[i];
        m = fmaxf(fmaxf(fabsf(v.x), fabsf(v.y)), fmaxf(fabsf(v.z), fabsf(v.w)));
    }
#pragma unroll
    for (int o = 16; o; o >>= 1) m = fmaxf(m, __shfl_xor_sync(0xffffffffu, m, o));
    if ((threadIdx.x & 31) == 0 && m > 0.0f)
        atomicMax(&g_amax[which], __float_as_uint(m));
}

// fp32 -> int8 symmetric quantization with global scale 127/amax
__global__ void quant_kernel(const float4* __restrict__ in, uint4* __restrict__ out,
                             int n16, int which)
{
    int i = blockIdx.x * blockDim.x + threadIdx.x;
    if (i >= n16) return;
    float sx = 127.0f / __uint_as_float(g_amax[which]);
    u32 w[4];
#pragma unroll
    for (int j = 0; j < 4; j++) {
        float4 v = in[4 * i + j];
        int q0 = max(-127, min(127, __float2int_rn(v.x * sx)));
        int q1 = max(-127, min(127, __float2int_rn(v.y * sx)));
        int q2 = max(-127, min(127, __float2int_rn(v.z * sx)));
        int q3 = max(-127, min(127, __float2int_rn(v.w * sx)));
        w[j] = (q0 & 0xFF) | ((q1 & 0xFF) << 8) | ((q2 & 0xFF) << 16) | ((q3 & 0xFF) << 24);
    }
    uint4 o; o.x = w[0]; o.y = w[1]; o.z = w[2]; o.w = w[3];
    out[i] = o;
}

// per-row quantization-residual norms (rigorous bound inputs, x1.001 margin)
__global__ void bound_kernel(const float* __restrict__ in, const char* __restrict__ q,
                             int rows, int which)
{
    int r = blockIdx.x * blockDim.x + threadIdx.x;
    if (r >= rows) return;
    float inv = __uint_as_float(g_amax[which]) / 127.0f;
    const float4* xp = (const float4*)(in + (size_t)r * DDIM);
    const uint4*  qp = (const uint4*)(q + (size_t)r * DDIM);
    float ssd = 0.0f, ssn = 0.0f;
#pragma unroll 4
    for (int i = 0; i < 16; i++) {
        uint4 qq = qp[i];
        u32 qs[4] = { qq.x, qq.y, qq.z, qq.w };
#pragma unroll
        for (int j = 0; j < 4; j++) {
            float4 v = xp[4 * i + j];
            u32 b = qs[j];
            float h0 = (float)((int)(signed char)(b))        * inv;
            float h1 = (float)((int)(signed char)(b >> 8))   * inv;
            float h2 = (float)((int)(signed char)(b >> 16))  * inv;
            float h3 = (float)((int)(signed char)(b >> 24))  * inv;
            float d0 = v.x - h0, d1 = v.y - h1, d2 = v.z - h2, d3 = v.w - h3;
            ssd += d0 * d0 + d1 * d1 + d2 * d2 + d3 * d3;
            ssn += h0 * h0 + h1 * h1 + h2 * h2 + h3 * h3;
        }
    }
    float ed = sqrtf(ssd) * 1.001f;
    if (which == 0) g_ex[r] = ed;
    else {
        float nn = sqrtf(ssn) * 1.001f;
        atomicMax(&g_maxw[0], __float_as_uint(nn));
        atomicMax(&g_maxw[1], __float_as_uint(ed));
    }
}

// ---------------------------------------------------------------------------
// Main tensor kernel: S32[128 rows x 128 codes] = xq.wq^T via IMMA m16n8k32,
// cp.async double-buffered K pipeline (4 stages of K=64 bytes). Epilogue:
// s = s32 * invscale (exact int sum), d2a = fl(fmaf(s,-2,x2)+w2); per-row min
// + approx atomicMin; push contenders with d2a <= ref + 4*Bs_r + 3e-4
// (rigorous superset of exact winners/ties; verified exactly downstream).
// ---------------------------------------------------------------------------
__global__ __launch_bounds__(THREADS, 2)
void vq_tensor_kernel()
{
    extern __shared__ float smf[];
    const u32 smem_base = smem_u32(smf);
    const int tid  = threadIdx.x;
    const int lane = tid & 31;
    const int wid  = tid >> 5;
    const int gid  = lane >> 2;        // 0..7
    const int tig  = lane & 3;         // 0..3
    const int warp_m = wid >> 2;       // 0..1 -> 64-row half
    const int warp_n = wid & 3;        // 0..3 -> 32-col quarter
    const int kBase = blockIdx.x * BN;
    const int mBase = blockIdx.y * BM;

    int acc[4][4][4];
#pragma unroll
    for (int mt = 0; mt < 4; mt++)
#pragma unroll
        for (int nt = 0; nt < 4; nt++)
#pragma unroll
            for (int i = 0; i < 4; i++) acc[mt][nt][i] = 0;

    // ---- async stage loader: A 128x64B + B 128x64B int8 tiles ----
    auto load_stage = [&](int buf, int k0) {
        u32 aB = smem_base + (u32)(buf * 2 * STG_B);
        u32 bB = aB + (u32)STG_B;
#pragma unroll
        for (int s = 0; s < 2; s++) {
            int g = tid + s * THREADS;          // 0..511
            int row = g >> 2, c = g & 3;        // 4 x 16B chunks per row
            cp16(aB + row * ASTRIDE + c * 16,
                 g_xq + (size_t)(mBase + row) * DDIM + k0 + c * 16);
            cp16(bB + row * ASTRIDE + c * 16,
                 g_wq + (size_t)(kBase + row) * DDIM + k0 + c * 16);
        }
    };

    load_stage(0, 0);  cp_commit();
    load_stage(1, KS); cp_commit();

#pragma unroll 1
    for (int s = 0; s < NSTEPS; s++) {
        if (s < NSTEPS - 1) cp_wait1(); else cp_wait0();
        __syncthreads();

        const char* A = (const char*)smf + (s & 1) * 2 * STG_B;
        const char* B = A + STG_B;
#pragma unroll
        for (int kk = 0; kk < 2; kk++) {        // two k32 steps per stage
            int koff = kk * 32 + 4 * tig;
            u32 af[4][4], bf[4][2];
#pragma unroll
            for (int mt = 0; mt < 4; mt++) {
                const char* base = A + (warp_m * 64 + mt * 16 + gid) * ASTRIDE + koff;
                af[mt][0] = *(const u32*)(base);
                af[mt][1] = *(const u32*)(base + 8 * ASTRIDE);
                af[mt][2] = *(const u32*)(base + 16);
                af[mt][3] = *(const u32*)(base + 8 * ASTRIDE + 16);
            }
#pragma unroll
            for (int nt = 0; nt < 4; nt++) {
                const char* bb = B + (warp_n * 32 + nt * 8 + gid) * ASTRIDE + koff;
                bf[nt][0] = *(const u32*)(bb);
                bf[nt][1] = *(const u32*)(bb + 16);
            }
#pragma unroll
            for (int mt = 0; mt < 4; mt++)
#pragma unroll
                for (int nt = 0; nt < 4; nt++)
                    mma_s8(acc[mt][nt], af[mt], bf[nt]);
        }
        __syncthreads();
        if (s + 2 < NSTEPS) { load_stage(s & 1, (s + 2) * KS); cp_commit(); }
    }

    // ---- epilogue: dequant + d2a bits to smem [128][ESTRIDE] ----
    const float invs = (__uint_as_float(g_amax[0]) * __uint_as_float(g_amax[1])) / 16129.0f;
    u32* d2s = (u32*)smf;
    {
        float x2v[4][2], w2v[4][2];
#pragma unroll
        for (int mt = 0; mt < 4; mt++) {
            int r = warp_m * 64 + mt * 16 + gid;
            x2v[mt][0] = g_x2[mBase + r];
            x2v[mt][1] = g_x2[mBase + r + 8];
        }
#pragma unroll
        for (int nt = 0; nt < 4; nt++) {
            int c = warp_n * 32 + nt * 8 + 2 * tig;
            w2v[nt][0] = g_w2[kBase + c];
            w2v[nt][1] = g_w2[kBase + c + 1];
        }
#pragma unroll
        for (int mt = 0; mt < 4; mt++) {
            int r = warp_m * 64 + mt * 16 + gid;
#pragma unroll
            for (int nt = 0; nt < 4; nt++) {
                int c = warp_n * 32 + nt * 8 + 2 * tig;
                float s00 = (float)acc[mt][nt][0] * invs;
                float s01 = (float)acc[mt][nt][1] * invs;
                float s10 = (float)acc[mt][nt][2] * invs;
                float s11 = (float)acc[mt][nt][3] * invs;
                float d00 = __fadd_rn(fmaf(s00, -2.0f, x2v[mt][0]), w2v[nt][0]);
                float d01 = __fadd_rn(fmaf(s01, -2.0f, x2v[mt][0]), w2v[nt][1]);
                float d10 = __fadd_rn(fmaf(s10, -2.0f, x2v[mt][1]), w2v[nt][0]);
                float d11 = __fadd_rn(fmaf(s11, -2.0f, x2v[mt][1]), w2v[nt][1]);
                d2s[r * ESTRIDE + c]           = __float_as_uint(d00);
                d2s[r * ESTRIDE + c + 1]       = __float_as_uint(d01);
                d2s[(r + 8) * ESTRIDE + c]     = __float_as_uint(d10);
                d2s[(r + 8) * ESTRIDE + c + 1] = __float_as_uint(d11);
            }
        }
    }
    __syncthreads();

    // ---- per-row scan: local min, approx atomicMin, contender pushes ----
    if (tid < BM) {
        int grow = mBase + tid;
        const u32* rowp = d2s + tid * ESTRIDE;
        u32 minb = 0xFFFFFFFFu; int mincol = 0;
#pragma unroll 4
        for (int c = 0; c < BN; c++) {
            u32 b = rowp[c];
            if (b < minb) { minb = b; mincol = c; }
        }
        u64 lkey = ((u64)minb << 13) | (u64)(kBase + mincol);
        u64 old = atomicMin(&g_key[grow], lkey);
        u32 gbits = (u32)(old >> 13);
        float ref_f = fminf(__uint_as_float(minb), __uint_as_float(gbits));
        float Bs = g_ex[grow] * __uint_as_float(g_maxw[0])
                 + sqrtf(g_x2[grow]) * 1.0001f * __uint_as_float(g_maxw[1]);
        float tf = ref_f + 4.0f * Bs + 3e-4f;
#pragma unroll 4
        for (int c = 0; c < BN; c++) {
            u32 b = rowp[c];
            if (__uint_as_float(b) <= tf) {
                int slot = atomicAdd(&g_cnt[grow], 1);
                if (slot < CAP)
                    g_list[(size_t)grow * CAP + slot] = ((u64)b << 13) | (u64)(kBase + c);
            }
        }
    }
}

// ---------------------------------------------------------------------------
// Exact dist2 via the ascending-d fmaf chain (bit-identical to the passing
// R11-R16 kernels' math).
// ---------------------------------------------------------------------------
__device__ __forceinline__ u64 exact_key(const float4* __restrict__ xp,
                                         const float* __restrict__ w,
                                         float x2r, int k)
{
    const float4* wp = (const float4*)(w + (size_t)k * DDIM);
    float s = 0.0f;
#pragma unroll 8
    for (int j = 0; j < DDIM / 4; j++) {
        float4 a = xp[j], b = wp[j];
        s = fmaf(a.x, b.x, s);
        s = fmaf(a.y, b.y, s);
        s = fmaf(a.z, b.z, s);
        s = fmaf(a.w, b.w, s);
    }
    float t  = fmaf(s, -2.0f, x2r);
    float d2 = __fadd_rn(t, g_w2[k]);
    return ((u64)__float_as_uint(d2) << 13) | (u64)k;
}

// ---------------------------------------------------------------------------
// Verify: re-filter the list against listmin + 4*Bs + 3e-4, recompute those
// exactly, take exact (d2bits,k) min. Full-scan fallback on list overflow.
// ---------------------------------------------------------------------------
__global__ void vq_verify_kernel(const float* __restrict__ x, const float* __restrict__ w)
{
    int row = blockIdx.x * blockDim.x + threadIdx.x;
    if (row >= NROWS) return;
    float x2r = g_x2[row];
    const float4* xp = (const float4*)(x + (size_t)row * DDIM);
    u64 best = ~0ULL;
    int cnt = g_cnt[row];

    if (cnt <= CAP) {
        const u64* lst = g_list + (size_t)row * CAP;
        u32 minb = 0xFFFFFFFFu;
        for (int i = 0; i < cnt; i++) {
            u32 b = (u32)(lst[i] >> 13);
            if (b < minb) minb = b;
        }
        float Bs = g_ex[row] * __uint_as_float(g_maxw[0])
                 + sqrtf(x2r) * 1.0001f * __uint_as_float(g_maxw[1]);
        float tf = __uint_as_float(minb) + 4.0f * Bs + 3e-4f;
        for (int i = 0; i < cnt; i++) {
            u64 key = lst[i];
            if (__uint_as_float((u32)(key >> 13)) > tf) continue;
            u64 ek = exact_key(xp, w, x2r, (int)(key & 0x1FFF));
            if (ek < best) best = ek;
        }
    } else {
        for (int k = 0; k < KCODES; k++) {
            u64 ek = exact_key(xp, w, x2r, k);
            if (ek < best) best = ek;
        }
    }
    g_key[row] = best;
}

// ---------------------------------------------------------------------------
// Output epilogue: out = [z_q (N), z (N), x (N), indices-as-float (R)]
// ---------------------------------------------------------------------------
__global__ void vq_epilogue_kernel(const float* __restrict__ x, const float* __restrict__ w,
                                   float* __restrict__ out, int N, int full)
{
    int t = blockIdx.x * blockDim.x + threadIdx.x;
    if (t >= N) return;
    int r = t >> 8;
    int d = t & 255;
    int k = (int)(g_key[r] & 0x1FFF);
    float z  = w[(size_t)k * DDIM + d];
    float xv = x[t];
    float zq = __fadd_rn(xv, __fsub_rn(z, xv));
    out[t] = zq;
    if (full) {
        out[(size_t)N + t]     = z;
        out[2 * (size_t)N + t] = xv;
        if (d == 0) out[3 * (size_t)N + r] = (float)k;
    }
}

__global__ void vq_idx_only_kernel(int* __restrict__ out, int R)
{
    int r = blockIdx.x * blockDim.x + threadIdx.x;
    if (r < R) out[r] = (int)(g_key[r] & 0x1FFF);
}

extern "C" void kernel_launch(void* const* d_in, const int* in_sizes, int n_in,
                              void* d_out, int out_size)
{
    const float* x  = (const float*)d_in[0];
    const float* cb = (const float*)d_in[1];
    int N  = in_sizes[0];        // 4194304
    int KD = KCODES * DDIM;      // 2097152
    int R  = N / DDIM;           // 16384

    cudaFuncSetAttribute(vq_tensor_kernel,
                         cudaFuncAttributeMaxDynamicSharedMemorySize, SMEM_BYTES);

    char *xq, *wq;
    cudaGetSymbolAddress((void**)&xq, g_xq);
    cudaGetSymbolAddress((void**)&wq, g_wq);

    // 1) row sums of squares + per-replay scratch re-init
    rowsq_kernel<<<(R + 127) / 128, 128>>>(x, R, 0);
    rowsq_kernel<<<(KCODES + 127) / 128, 128>>>(cb, KCODES, 1);

    // 2) global amax of each tensor
    amax_kernel<<<(N / 4 + 255) / 256, 256>>>((const float4*)x, N / 4, 0);
    amax_kernel<<<(KD / 4 + 255) / 256, 256>>>((const float4*)cb, KD / 4, 1);

    // 3) int8 symmetric quantization
    quant_kernel<<<(N / 16 + 255) / 256, 256>>>((const float4*)x, (uint4*)xq, N / 16, 0);
    quant_kernel<<<(KD / 16 + 255) / 256, 256>>>((const float4*)cb, (uint4*)wq, KD / 16, 1);

    // 4) rigorous per-row residual norms (bound inputs)
    bound_kernel<<<(R + 127) / 128, 128>>>(x, xq, R, 0);
    bound_kernel<<<(KCODES + 127) / 128, 128>>>(cb, wq, KCODES, 1);

    // 5) int8 tensor GEMM + approx argmin + contender collection
    dim3 grid(KCODES / BN, R / BM);
    vq_tensor_kernel<<<grid, THREADS, SMEM_BYTES>>>();

    // 6) exact verification of contenders (bit-exact argmin)
    vq_verify_kernel<<<(R + 127) / 128, 128>>>(x, cb);

    // 7) write outputs
    if (out_size >= N) {
        int full = (out_size >= 3 * N + R) ? 1 : 0;
        vq_epilogue_kernel<<<(N + 255) / 256, 256>>>(x, cb, (float*)d_out, N, full);
    } else {
        vq_idx_only_kernel<<<(R + 255) / 256, 256>>>((int*)d_out,
                                                     out_size < R ? out_size : R);
    }
}